// round 10
// baseline (speedup 1.0000x reference)
#include <cuda_runtime.h>
#include <cstdint>

#define BATCH   16384
#define NIN     784
#define TSTEPS  100
#define NOUT    10
#define IPAD    12          // padded o-stride for 16B-aligned stores

// ---- scratch (static device globals: allocation-free) ----
__device__ unsigned g_xi[BATCH * NIN];                       // 51.4 MB: ceil(x * 2^23)
__device__ float    g_I[(size_t)TSTEPS * BATCH * IPAD];      // 78.6 MB: I[t][b][o]

struct U2 { unsigned a, b; };

// plain threefry (used once per thread for the foldlike split key)
__device__ __forceinline__ unsigned rotl32(unsigned v, int s) {
    return __funnelshift_l(v, v, s);
}
__device__ __forceinline__ U2 threefry2x32(unsigned k0, unsigned k1,
                                           unsigned c0, unsigned c1) {
    unsigned k2 = k0 ^ k1 ^ 0x1BD11BDAu;
    unsigned x0 = c0 + k0;
    unsigned x1 = c1 + k1;
#define TFR(r) { x0 += x1; x1 = rotl32(x1, (r)) ^ x0; }
    TFR(13) TFR(15) TFR(26) TFR(6)
    x0 += k1; x1 += k2 + 1u;
    TFR(17) TFR(29) TFR(16) TFR(24)
    x0 += k2; x1 += k0 + 2u;
    TFR(13) TFR(15) TFR(26) TFR(6)
    x0 += k0; x1 += k1 + 3u;
    TFR(17) TFR(29) TFR(16) TFR(24)
    x0 += k1; x1 += k2 + 4u;
    TFR(13) TFR(15) TFR(26) TFR(6)
    x0 += k2; x1 += k0 + 5u;
#undef TFR
    return {x0, x1};
}

// ---------------- phase 0: x -> integer spike thresholds ----------------
// spike <=> u < x <=> (bits>>9) < ceil(x*2^23); bit-exact (see prior rounds).
__global__ __launch_bounds__(256) void snn_prep(const float* __restrict__ x) {
    int i = blockIdx.x * 256 + threadIdx.x;
    if (i < BATCH * NIN)
        g_xi[i] = __float2uint_ru(x[i] * 8388608.0f);
}

// Rotate-by-s via IMAD.WIDE (fma pipe) + single LOP3 (lo|hi)^x0 (alu pipe).
// c holds 1u<<s, de-folded via shared memory so ptxas cannot strength-reduce
// the wide multiply back into SHF on the alu pipe.
// Exactness: v*2^s as u64 has lo = v<<s, hi = v>>(32-s); lo|hi == rotl32(v,s).
#define TFROUND(x0, x1, c) do {                                        \
    unsigned long long _w;                                             \
    x0 += x1;                                                          \
    asm("mul.wide.u32 %0, %1, %2;" : "=l"(_w) : "r"(x1), "r"(c));      \
    x1 = ((unsigned)_w | (unsigned)(_w >> 32)) ^ x0;                   \
} while (0)

// ---------------- phase 1: per-(b,t) Poisson encode + spike matvec ----------------
__global__ __launch_bounds__(256) void snn_phase1(const float* __restrict__ W) {
    // W packed as f32x2 o-pairs: s_w2[i*6 + k] = {W[2k][i], W[2k+1][i]}
    // row padded to 6 (48B -> LDS.128 x2 + LDS.64 per row). 37,632 B shared.
    __shared__ unsigned long long s_w2[NIN * 6];
    __shared__ unsigned s_pw[8];     // de-folded rotation multipliers 1<<s

    if (threadIdx.x < 8) {
        const unsigned char sh[8] = {13, 15, 26, 6, 17, 29, 16, 24};
        s_pw[threadIdx.x] = 1u << sh[threadIdx.x];
    }
    for (int idx = threadIdx.x; idx < NIN * 5; idx += 256) {
        int i = idx / 5, k = idx - 5 * (idx / 5);
        float lo = W[(2 * k)     * NIN + i];
        float hi = W[(2 * k + 1) * NIN + i];
        unsigned long long p;
        asm("mov.b64 %0, {%1, %2};" : "=l"(p) : "f"(lo), "f"(hi));
        s_w2[i * 6 + k] = p;
    }
    __syncthreads();

    const unsigned cA0 = s_pw[0], cA1 = s_pw[1], cA2 = s_pw[2], cA3 = s_pw[3];
    const unsigned cB0 = s_pw[4], cB1 = s_pw[5], cB2 = s_pw[6], cB3 = s_pw[7];

    int item = blockIdx.x * 256 + threadIdx.x;   // exactly BATCH*TSTEPS items
    int b = item / TSTEPS;
    int t = item - b * TSTEPS;

    // foldlike split: key_t = full output pair of threefry((0,42), (0,t))
    U2 kt = threefry2x32(0u, 42u, 0u, (unsigned)t);
    const unsigned k0 = kt.a, k1 = kt.b;
    const unsigned k2   = k0 ^ k1 ^ 0x1BD11BDAu;
    const unsigned k2p1 = k2 + 1u, k0p2 = k0 + 2u, k1p3 = k1 + 3u;
    const unsigned k2p4 = k2 + 4u, k0p5 = k0 + 5u;

    unsigned long long acc[5];
#pragma unroll
    for (int k = 0; k < 5; k++) acc[k] = 0ull;

    const unsigned* __restrict__ xip = g_xi + b * NIN;   // lanes share b -> L1 broadcast
    const unsigned idx0 = (unsigned)(b * NIN);           // flat iota base

    for (int i0 = 0; i0 < NIN; i0 += 4) {
        uint4 xi4 = *(const uint4*)(xip + i0);
#pragma unroll
        for (int u = 0; u < 4; u++) {
            unsigned xi = (u == 0) ? xi4.x : (u == 1) ? xi4.y : (u == 2) ? xi4.z : xi4.w;
            // partitionable 32-bit random_bits: out0^out1, counter (0, j), c0 = 0
            unsigned x0 = k0;
            unsigned x1 = k1 + (idx0 + (unsigned)(i0 + u));
            TFROUND(x0, x1, cA0); TFROUND(x0, x1, cA1);
            TFROUND(x0, x1, cA2); TFROUND(x0, x1, cA3);
            x1 += k2p1; x0 += k1;            // x0-add merges into next round's IADD3
            TFROUND(x0, x1, cB0); TFROUND(x0, x1, cB1);
            TFROUND(x0, x1, cB2); TFROUND(x0, x1, cB3);
            x1 += k0p2; x0 += k2;
            TFROUND(x0, x1, cA0); TFROUND(x0, x1, cA1);
            TFROUND(x0, x1, cA2); TFROUND(x0, x1, cA3);
            x1 += k1p3; x0 += k0;
            TFROUND(x0, x1, cB0); TFROUND(x0, x1, cB1);
            TFROUND(x0, x1, cB2); TFROUND(x0, x1, cB3);
            x1 += k2p4; x0 += k1;
            TFROUND(x0, x1, cA0); TFROUND(x0, x1, cA1);
            TFROUND(x0, x1, cA2); TFROUND(x0, x1, cA3);
            x1 += k0p5; x0 += k2;

            unsigned m = (x0 ^ x1) >> 9;     // 23 mantissa bits

            const unsigned long long* wr = s_w2 + (i0 + u) * 6;
            ulonglong2 w01 = *(const ulonglong2*)(wr);       // LDS.128
            ulonglong2 w23 = *(const ulonglong2*)(wr + 2);   // LDS.128
            unsigned long long w4 = wr[4];                   // LDS.64
            // spike => acc[k] += w[k] (packed f32x2, predicated; bit-exact:
            // acc unchanged on no-spike, acc+w == fma(1,w,acc) on spike)
            asm("{\n\t"
                ".reg .pred p;\n\t"
                "setp.lt.u32 p, %5, %6;\n\t"
                "@p add.rn.f32x2 %0, %0, %7;\n\t"
                "@p add.rn.f32x2 %1, %1, %8;\n\t"
                "@p add.rn.f32x2 %2, %2, %9;\n\t"
                "@p add.rn.f32x2 %3, %3, %10;\n\t"
                "@p add.rn.f32x2 %4, %4, %11;\n\t"
                "}"
                : "+l"(acc[0]), "+l"(acc[1]), "+l"(acc[2]),
                  "+l"(acc[3]), "+l"(acc[4])
                : "r"(m), "r"(xi),
                  "l"(w01.x), "l"(w01.y), "l"(w23.x), "l"(w23.y), "l"(w4));
        }
    }

    // I[t][b][0..9], padded stride 12 -> base byte offset multiple of 48
    unsigned long long* dst =
        (unsigned long long*)(g_I + ((size_t)t * BATCH + b) * IPAD);
#pragma unroll
    for (int k = 0; k < 5; k++) dst[k] = acc[k];
}

// ---------------- phase 2: LIF scan over t, per (b,o) ----------------
__global__ __launch_bounds__(256) void snn_phase2(float* __restrict__ out) {
    int id = blockIdx.x * 256 + threadIdx.x;
    if (id >= BATCH * NOUT) return;
    int b = id / NOUT, o = id - b * NOUT;
    const float* __restrict__ src = g_I + (size_t)b * IPAD + o;

    float v = 0.0f, acc = 0.0f;
#pragma unroll 4
    for (int t = 0; t < TSTEPS; t++) {
        float I = src[(size_t)t * BATCH * IPAD];
        v = v + (I - v) * 0.5f;          // /2.0 == *0.5 exactly
        if (v >= 1.0f) { acc += 1.0f; v = 0.0f; }   // sign-exact vs (v-1>=0)
    }
    out[id] = __fdiv_rn(acc, 100.0f);    // IEEE div regardless of fast-math flags
}

// ---------------- launch ----------------
extern "C" void kernel_launch(void* const* d_in, const int* in_sizes, int n_in,
                              void* d_out, int out_size) {
    const float* x = (const float*)d_in[0];
    const float* W = (const float*)d_in[1];
    if (n_in >= 2 && in_sizes[0] == NOUT * NIN) {   // order robustness
        W = (const float*)d_in[0];
        x = (const float*)d_in[1];
    }
    float* out = (float*)d_out;               // [16384,10]

    snn_prep  <<<(BATCH * NIN + 255) / 256, 256>>>(x);
    snn_phase1<<<(BATCH * TSTEPS) / 256,    256>>>(W);
    snn_phase2<<<(BATCH * NOUT + 255) / 256, 256>>>(out);
}

// round 12
// speedup vs baseline: 1.1975x; 1.1975x over previous
#include <cuda_runtime.h>
#include <cstdint>

#define BATCH   16384
#define NIN     784
#define TSTEPS  100
#define NOUT    10
#define IPAD    12          // padded o-stride for 16B-aligned stores

// ---- scratch (static device globals: allocation-free) ----
__device__ unsigned g_xi[BATCH * NIN];                       // 51.4 MB: ceil(x * 2^23)
__device__ float    g_I[(size_t)TSTEPS * BATCH * IPAD];      // 78.6 MB: I[t][b][o]

struct U2 { unsigned a, b; };

// plain threefry (used once per thread for the foldlike split key)
__device__ __forceinline__ unsigned rotl32(unsigned v, int s) {
    return __funnelshift_l(v, v, s);
}
__device__ __forceinline__ U2 threefry2x32(unsigned k0, unsigned k1,
                                           unsigned c0, unsigned c1) {
    unsigned k2 = k0 ^ k1 ^ 0x1BD11BDAu;
    unsigned x0 = c0 + k0;
    unsigned x1 = c1 + k1;
#define TFR(r) { x0 += x1; x1 = rotl32(x1, (r)) ^ x0; }
    TFR(13) TFR(15) TFR(26) TFR(6)
    x0 += k1; x1 += k2 + 1u;
    TFR(17) TFR(29) TFR(16) TFR(24)
    x0 += k2; x1 += k0 + 2u;
    TFR(13) TFR(15) TFR(26) TFR(6)
    x0 += k0; x1 += k1 + 3u;
    TFR(17) TFR(29) TFR(16) TFR(24)
    x0 += k1; x1 += k2 + 4u;
    TFR(13) TFR(15) TFR(26) TFR(6)
    x0 += k2; x1 += k0 + 5u;
#undef TFR
    return {x0, x1};
}

// ---------------- phase 0: x -> integer spike thresholds ----------------
// spike <=> u < x <=> (bits>>9) < ceil(x*2^23); bit-exact (see prior rounds).
__global__ __launch_bounds__(256) void snn_prep(const float* __restrict__ x) {
    int i = blockIdx.x * 256 + threadIdx.x;
    if (i < BATCH * NIN)
        g_xi[i] = __float2uint_ru(x[i] * 8388608.0f);
}

// Threefry round with the add FORCED onto the fma pipe as IMAD:
// x0 = x1*one + x0 (one == 1, de-folded via shared memory so ptxas must emit
// IMAD, not IADD3). Rotate stays SHF (alu, rt=2 — wide-mul rotates measured
// SLOWER in R10). The rotate reads x1_old, so SHF and IMAD issue in parallel.
#define TFROUND_F(x0, x1, r, one) do {                                      \
    asm("mad.lo.u32 %0, %1, %2, %0;" : "+r"(x0) : "r"(x1), "r"(one));       \
    x1 = __funnelshift_l(x1, x1, (r)) ^ x0;                                 \
} while (0)

// Key-injection add, also forced to IMAD (fma pipe).
#define INJ(v, k, one) \
    asm("mad.lo.u32 %0, %1, %2, %0;" : "+r"(v) : "r"(k), "r"(one))

// ---------------- phase 1: per-(b,t) Poisson encode + spike matvec ----------------
__global__ __launch_bounds__(256) void snn_phase1(const float* __restrict__ W) {
    // W packed as f32x2 o-pairs: s_w2[i*6 + k] = {W[2k][i], W[2k+1][i]}
    // row padded to 6 (48B -> LDS.128 x2 + LDS.64 per row). 37,632 B shared.
    __shared__ unsigned long long s_w2[NIN * 6];
    __shared__ unsigned s_one[1];    // de-folded constant 1 (IMAD forcing)

    if (threadIdx.x == 0) s_one[0] = 1u;
    for (int idx = threadIdx.x; idx < NIN * 5; idx += 256) {
        int i = idx / 5, k = idx - 5 * (idx / 5);
        float lo = W[(2 * k)     * NIN + i];
        float hi = W[(2 * k + 1) * NIN + i];
        unsigned long long p;
        asm("mov.b64 %0, {%1, %2};" : "=l"(p) : "f"(lo), "f"(hi));
        s_w2[i * 6 + k] = p;
    }
    __syncthreads();

    const unsigned c1 = s_one[0];    // runtime "1" -> IMADs survive ptxas

    int item = blockIdx.x * 256 + threadIdx.x;   // exactly BATCH*TSTEPS items
    int b = item / TSTEPS;
    int t = item - b * TSTEPS;

    // foldlike split: key_t = full output pair of threefry((0,42), (0,t))
    U2 kt = threefry2x32(0u, 42u, 0u, (unsigned)t);
    const unsigned k0 = kt.a, k1 = kt.b;
    const unsigned k2   = k0 ^ k1 ^ 0x1BD11BDAu;
    const unsigned k2p1 = k2 + 1u, k0p2 = k0 + 2u, k1p3 = k1 + 3u;
    const unsigned k2p4 = k2 + 4u, k0p5 = k0 + 5u;

    unsigned long long acc[5];
#pragma unroll
    for (int k = 0; k < 5; k++) acc[k] = 0ull;

    const unsigned* __restrict__ xip = g_xi + b * NIN;   // lanes share b -> L1 broadcast
    const unsigned idx0 = (unsigned)(b * NIN);           // flat iota base

    for (int i0 = 0; i0 < NIN; i0 += 4) {
        uint4 xi4 = *(const uint4*)(xip + i0);
#pragma unroll
        for (int u = 0; u < 4; u++) {
            unsigned xi = (u == 0) ? xi4.x : (u == 1) ? xi4.y : (u == 2) ? xi4.z : xi4.w;
            // partitionable 32-bit random_bits: out0^out1, counter (0, j), c0 = 0
            unsigned x0 = k0;
            unsigned x1 = k1 + (idx0 + (unsigned)(i0 + u));
            TFROUND_F(x0, x1, 13, c1); TFROUND_F(x0, x1, 15, c1);
            TFROUND_F(x0, x1, 26, c1); TFROUND_F(x0, x1,  6, c1);
            INJ(x0, k1, c1); INJ(x1, k2p1, c1);
            TFROUND_F(x0, x1, 17, c1); TFROUND_F(x0, x1, 29, c1);
            TFROUND_F(x0, x1, 16, c1); TFROUND_F(x0, x1, 24, c1);
            INJ(x0, k2, c1); INJ(x1, k0p2, c1);
            TFROUND_F(x0, x1, 13, c1); TFROUND_F(x0, x1, 15, c1);
            TFROUND_F(x0, x1, 26, c1); TFROUND_F(x0, x1,  6, c1);
            INJ(x0, k0, c1); INJ(x1, k1p3, c1);
            TFROUND_F(x0, x1, 17, c1); TFROUND_F(x0, x1, 29, c1);
            TFROUND_F(x0, x1, 16, c1); TFROUND_F(x0, x1, 24, c1);
            INJ(x0, k1, c1); INJ(x1, k2p4, c1);
            TFROUND_F(x0, x1, 13, c1); TFROUND_F(x0, x1, 15, c1);
            TFROUND_F(x0, x1, 26, c1); TFROUND_F(x0, x1,  6, c1);
            INJ(x0, k2, c1); INJ(x1, k0p5, c1);

            unsigned m = (x0 ^ x1) >> 9;     // 23 mantissa bits

            const unsigned long long* wr = s_w2 + (i0 + u) * 6;
            ulonglong2 w01 = *(const ulonglong2*)(wr);       // LDS.128
            ulonglong2 w23 = *(const ulonglong2*)(wr + 2);   // LDS.128
            unsigned long long w4 = wr[4];                   // LDS.64
            // spike => acc[k] += w[k] (packed f32x2, predicated; bit-exact:
            // acc unchanged on no-spike, acc+w == fma(1,w,acc) on spike)
            asm("{\n\t"
                ".reg .pred p;\n\t"
                "setp.lt.u32 p, %5, %6;\n\t"
                "@p add.rn.f32x2 %0, %0, %7;\n\t"
                "@p add.rn.f32x2 %1, %1, %8;\n\t"
                "@p add.rn.f32x2 %2, %2, %9;\n\t"
                "@p add.rn.f32x2 %3, %3, %10;\n\t"
                "@p add.rn.f32x2 %4, %4, %11;\n\t"
                "}"
                : "+l"(acc[0]), "+l"(acc[1]), "+l"(acc[2]),
                  "+l"(acc[3]), "+l"(acc[4])
                : "r"(m), "r"(xi),
                  "l"(w01.x), "l"(w01.y), "l"(w23.x), "l"(w23.y), "l"(w4));
        }
    }

    // I[t][b][0..9], padded stride 12 -> base byte offset multiple of 48
    unsigned long long* dst =
        (unsigned long long*)(g_I + ((size_t)t * BATCH + b) * IPAD);
#pragma unroll
    for (int k = 0; k < 5; k++) dst[k] = acc[k];
}

// ---------------- phase 2: LIF scan over t, per (b,o) ----------------
__global__ __launch_bounds__(256) void snn_phase2(float* __restrict__ out) {
    int id = blockIdx.x * 256 + threadIdx.x;
    if (id >= BATCH * NOUT) return;
    int b = id / NOUT, o = id - b * NOUT;
    const float* __restrict__ src = g_I + (size_t)b * IPAD + o;

    float v = 0.0f, acc = 0.0f;
#pragma unroll 4
    for (int t = 0; t < TSTEPS; t++) {
        float I = src[(size_t)t * BATCH * IPAD];
        v = v + (I - v) * 0.5f;          // /2.0 == *0.5 exactly
        if (v >= 1.0f) { acc += 1.0f; v = 0.0f; }   // sign-exact vs (v-1>=0)
    }
    out[id] = __fdiv_rn(acc, 100.0f);    // IEEE div regardless of fast-math flags
}

// ---------------- launch ----------------
extern "C" void kernel_launch(void* const* d_in, const int* in_sizes, int n_in,
                              void* d_out, int out_size) {
    const float* x = (const float*)d_in[0];
    const float* W = (const float*)d_in[1];
    if (n_in >= 2 && in_sizes[0] == NOUT * NIN) {   // order robustness
        W = (const float*)d_in[0];
        x = (const float*)d_in[1];
    }
    float* out = (float*)d_out;               // [16384,10]

    snn_prep  <<<(BATCH * NIN + 255) / 256, 256>>>(x);
    snn_phase1<<<(BATCH * TSTEPS) / 256,    256>>>(W);
    snn_phase2<<<(BATCH * NOUT + 255) / 256, 256>>>(out);
}

// round 14
// speedup vs baseline: 1.2379x; 1.0338x over previous
#include <cuda_runtime.h>
#include <cstdint>

#define BATCH   16384
#define NIN     784
#define TSTEPS  100
#define NOUT    10
#define IPAD    12          // padded o-stride for 16B-aligned stores

// ---- scratch (static device globals: allocation-free) ----
__device__ unsigned g_xi[BATCH * NIN];                       // 51.4 MB: (ceil(x*2^23))<<9
__device__ float    g_I[(size_t)TSTEPS * BATCH * IPAD];      // 78.6 MB: I[t][b][o]

struct U2 { unsigned a, b; };

__device__ __forceinline__ unsigned rotl32(unsigned v, int s) {
    return __funnelshift_l(v, v, s);
}
// plain threefry (used once per thread for the foldlike split key)
__device__ __forceinline__ U2 threefry2x32(unsigned k0, unsigned k1,
                                           unsigned c0, unsigned c1) {
    unsigned k2 = k0 ^ k1 ^ 0x1BD11BDAu;
    unsigned x0 = c0 + k0;
    unsigned x1 = c1 + k1;
#define TFR(r) { x0 += x1; x1 = rotl32(x1, (r)) ^ x0; }
    TFR(13) TFR(15) TFR(26) TFR(6)
    x0 += k1; x1 += k2 + 1u;
    TFR(17) TFR(29) TFR(16) TFR(24)
    x0 += k2; x1 += k0 + 2u;
    TFR(13) TFR(15) TFR(26) TFR(6)
    x0 += k0; x1 += k1 + 3u;
    TFR(17) TFR(29) TFR(16) TFR(24)
    x0 += k1; x1 += k2 + 4u;
    TFR(13) TFR(15) TFR(26) TFR(6)
    x0 += k2; x1 += k0 + 5u;
#undef TFR
    return {x0, x1};
}

// ---------------- phase 0: x -> pre-shifted integer spike thresholds --------
// spike <=> u < x <=> (bits>>9) < ceil(x*2^23) <=> bits < (ceil(x*2^23)<<9).
// Exact: x<1 strictly => T <= 2^23-1 => T<<9 < 2^32 (no overflow);
// bits>>9 < T  <=>  bits < T*512 (both directions, integer).
__global__ __launch_bounds__(256) void snn_prep(const float* __restrict__ x) {
    int i = blockIdx.x * 256 + threadIdx.x;
    if (i < BATCH * NIN)
        g_xi[i] = __float2uint_ru(x[i] * 8388608.0f) << 9;
}

// Threefry round, plain C: ptxas merges x0-injections into 3-input IADD3 and
// auto-balances IADD3/IMAD across pipes (R12 measured: forcing is neutral;
// total instruction count is what binds).
#define TFR(r) { x0 += x1; x1 = rotl32(x1, (r)) ^ x0; }

// ---------------- phase 1: per-(b,t) Poisson encode + spike matvec ----------
__global__ __launch_bounds__(256) void snn_phase1(const float* __restrict__ W) {
    // W packed as f32x2 o-pairs: s_w2[i*6 + k] = {W[2k][i], W[2k+1][i]}
    // row padded to 6 (48B): per row 2x LDS.128 + 1x LDS.64, broadcast.
    __shared__ unsigned long long s_w2[NIN * 6];
    for (int idx = threadIdx.x; idx < NIN * 5; idx += 256) {
        int i = idx / 5, k = idx - 5 * (idx / 5);
        float lo = W[(2 * k)     * NIN + i];
        float hi = W[(2 * k + 1) * NIN + i];
        unsigned long long p;
        asm("mov.b64 %0, {%1, %2};" : "=l"(p) : "f"(lo), "f"(hi));
        s_w2[i * 6 + k] = p;
    }
    __syncthreads();

    int item = blockIdx.x * 256 + threadIdx.x;   // exactly BATCH*TSTEPS items
    int b = item / TSTEPS;
    int t = item - b * TSTEPS;

    // foldlike split: key_t = full output pair of threefry((0,42), (0,t))
    U2 kt = threefry2x32(0u, 42u, 0u, (unsigned)t);
    const unsigned k0 = kt.a, k1 = kt.b;
    const unsigned k2   = k0 ^ k1 ^ 0x1BD11BDAu;
    const unsigned k2p1 = k2 + 1u, k0p2 = k0 + 2u, k1p3 = k1 + 3u;
    const unsigned k2p4 = k2 + 4u, k0p5 = k0 + 5u;

    const unsigned idx0 = (unsigned)(b * NIN);   // flat iota base
    // fold counter init into keys: x1 = D + iu, round-1 x0 = E + iu
    const unsigned D = k1 + idx0;                // x1 init base
    const unsigned E = k0 + k1 + idx0;           // x0 after round-1 add

    unsigned long long acc[5];
#pragma unroll
    for (int k = 0; k < 5; k++) acc[k] = 0ull;

    const unsigned* __restrict__ xip = g_xi + b * NIN;   // lanes share b -> L1 broadcast

    for (int i0 = 0; i0 < NIN; i0 += 8) {
        uint4 xiA = *(const uint4*)(xip + i0);
        uint4 xiB = *(const uint4*)(xip + i0 + 4);
        const unsigned long long* wr8 = s_w2 + i0 * 6;   // const-indexed below
#pragma unroll
        for (int u = 0; u < 8; u++) {
            unsigned xi =
                (u == 0) ? xiA.x : (u == 1) ? xiA.y : (u == 2) ? xiA.z :
                (u == 3) ? xiA.w : (u == 4) ? xiB.x : (u == 5) ? xiB.y :
                (u == 6) ? xiB.z : xiB.w;
            // partitionable 32-bit random_bits: out0^out1, counter (0, j)
            unsigned iu = (unsigned)u;           // i0 folded via wr8 / D+i0 below
            unsigned x1 = (D + (unsigned)i0) + iu;
            unsigned x0 = (E + (unsigned)i0) + iu;           // round-1 add folded
            x1 = rotl32(x1, 13) ^ x0;                        // finish round 1
            TFR(15) TFR(26) TFR(6)
            x0 += k1; x1 += k2p1;
            TFR(17) TFR(29) TFR(16) TFR(24)
            x0 += k2; x1 += k0p2;
            TFR(13) TFR(15) TFR(26) TFR(6)
            x0 += k0; x1 += k1p3;
            TFR(17) TFR(29) TFR(16) TFR(24)
            x0 += k1; x1 += k2p4;
            TFR(13) TFR(15) TFR(26) TFR(6)
            x0 += k2; x1 += k0p5;

            unsigned bits = x0 ^ x1;             // no shift: threshold pre-shifted

            ulonglong2 w01 = *(const ulonglong2*)(wr8 + u * 6);       // LDS.128 +imm
            ulonglong2 w23 = *(const ulonglong2*)(wr8 + u * 6 + 2);   // LDS.128 +imm
            unsigned long long w4 = wr8[u * 6 + 4];                   // LDS.64  +imm
            // spike => acc[k] += w[k] (packed f32x2, predicated; bit-exact:
            // acc unchanged on no-spike, acc+w == fma(1,w,acc) on spike)
            asm("{\n\t"
                ".reg .pred p;\n\t"
                "setp.lt.u32 p, %5, %6;\n\t"
                "@p add.rn.f32x2 %0, %0, %7;\n\t"
                "@p add.rn.f32x2 %1, %1, %8;\n\t"
                "@p add.rn.f32x2 %2, %2, %9;\n\t"
                "@p add.rn.f32x2 %3, %3, %10;\n\t"
                "@p add.rn.f32x2 %4, %4, %11;\n\t"
                "}"
                : "+l"(acc[0]), "+l"(acc[1]), "+l"(acc[2]),
                  "+l"(acc[3]), "+l"(acc[4])
                : "r"(bits), "r"(xi),
                  "l"(w01.x), "l"(w01.y), "l"(w23.x), "l"(w23.y), "l"(w4));
        }
    }

    // I[t][b][0..9], padded stride 12 -> base byte offset multiple of 48
    unsigned long long* dst =
        (unsigned long long*)(g_I + ((size_t)t * BATCH + b) * IPAD);
#pragma unroll
    for (int k = 0; k < 5; k++) dst[k] = acc[k];
}

// ---------------- phase 2: LIF scan over t, per (b,o) ----------------
__global__ __launch_bounds__(256) void snn_phase2(float* __restrict__ out) {
    int id = blockIdx.x * 256 + threadIdx.x;
    if (id >= BATCH * NOUT) return;
    int b = id / NOUT, o = id - b * NOUT;
    const float* __restrict__ src = g_I + (size_t)b * IPAD + o;

    float v = 0.0f, acc = 0.0f;
#pragma unroll 4
    for (int t = 0; t < TSTEPS; t++) {
        float I = src[(size_t)t * BATCH * IPAD];
        v = v + (I - v) * 0.5f;          // /2.0 == *0.5 exactly
        if (v >= 1.0f) { acc += 1.0f; v = 0.0f; }   // sign-exact vs (v-1>=0)
    }
    out[id] = __fdiv_rn(acc, 100.0f);    // IEEE div regardless of fast-math flags
}

// ---------------- launch ----------------
extern "C" void kernel_launch(void* const* d_in, const int* in_sizes, int n_in,
                              void* d_out, int out_size) {
    const float* x = (const float*)d_in[0];
    const float* W = (const float*)d_in[1];
    if (n_in >= 2 && in_sizes[0] == NOUT * NIN) {   // order robustness
        W = (const float*)d_in[0];
        x = (const float*)d_in[1];
    }
    float* out = (float*)d_out;               // [16384,10]

    snn_prep  <<<(BATCH * NIN + 255) / 256, 256>>>(x);
    snn_phase1<<<(BATCH * TSTEPS) / 256,    256>>>(W);
    snn_phase2<<<(BATCH * NOUT + 255) / 256, 256>>>(out);
}

// round 17
// speedup vs baseline: 1.5110x; 1.2206x over previous
#include <cuda_runtime.h>
#include <cstdint>

#define BATCH   16384
#define NIN     784
#define NPAIR   (NIN / 2)     // 392
#define TSTEPS  100
#define NOUT    10
#define IPAD    12            // padded o-stride for 16B-aligned stores

// ---- scratch (static device globals: allocation-free) ----
__device__ unsigned g_xi[BATCH * NIN];                       // (ceil(x*2^23))<<9
__device__ float    g_I[(size_t)TSTEPS * BATCH * IPAD];      // I[t][b][o]

struct U2 { unsigned a, b; };

__device__ __forceinline__ unsigned rotl32(unsigned v, int s) {
    return __funnelshift_l(v, v, s);
}
// plain threefry (once per thread, for the foldlike split key)
__device__ __forceinline__ U2 threefry2x32(unsigned k0, unsigned k1,
                                           unsigned c0, unsigned c1) {
    unsigned k2 = k0 ^ k1 ^ 0x1BD11BDAu;
    unsigned x0 = c0 + k0;
    unsigned x1 = c1 + k1;
#define TFRX(r) { x0 += x1; x1 = rotl32(x1, (r)) ^ x0; }
    TFRX(13) TFRX(15) TFRX(26) TFRX(6)
    x0 += k1; x1 += k2 + 1u;
    TFRX(17) TFRX(29) TFRX(16) TFRX(24)
    x0 += k2; x1 += k0 + 2u;
    TFRX(13) TFRX(15) TFRX(26) TFRX(6)
    x0 += k0; x1 += k1 + 3u;
    TFRX(17) TFRX(29) TFRX(16) TFRX(24)
    x0 += k1; x1 += k2 + 4u;
    TFRX(13) TFRX(15) TFRX(26) TFRX(6)
    x0 += k2; x1 += k0 + 5u;
#undef TFRX
    return {x0, x1};
}

// ---------------- phase 0: x -> pre-shifted integer spike thresholds --------
// spike <=> bits < (ceil(x*2^23)<<9); exact (validated R13).
__global__ __launch_bounds__(256) void snn_prep(const float* __restrict__ x) {
    int i = blockIdx.x * 256 + threadIdx.x;
    if (i < BATCH * NIN)
        g_xi[i] = __float2uint_ru(x[i] * 8388608.0f) << 9;
}

// threefry round on named state (plain C; ptxas merges injections into IADD3)
#define RND(a, b, r) { a += b; b = rotl32(b, (r)) ^ a; }

// ---------------- phase 1: pair-table Poisson encode + spike matvec ---------
// Pair table T: per input pair p, 4 entries of 10 packed f32 (as 5 ull + 8B pad,
// 48B stride): +0=zeros, +48=W_{2p}, +96=W_{2p+1}, +144=W_{2p}+W_{2p+1}.
// addr = base + 192p + (spikeA?48:0) + (spikeB?96:0); 5 UNPREDICATED packed adds.
// +0.0 adds are exact identities (acc never -0 under RN); grouped sum Wa+Wb is a
// summation-order change — same deviation class as the reference GEMM already has.
__global__ __launch_bounds__(256) void snn_phase1(const float* __restrict__ W) {
    extern __shared__ unsigned long long T[];     // NPAIR*24 ull = 75,264 B
    for (int idx = threadIdx.x; idx < NPAIR * 5; idx += 256) {
        int p = idx / 5, k = idx - 5 * p;
        int ia = 2 * p, ib = 2 * p + 1;
        float a0 = W[(2 * k)     * NIN + ia], a1 = W[(2 * k + 1) * NIN + ia];
        float b0 = W[(2 * k)     * NIN + ib], b1 = W[(2 * k + 1) * NIN + ib];
        float s0 = a0 + b0, s1 = a1 + b1;
        unsigned long long e1, e2, e3;
        asm("mov.b64 %0, {%1, %2};" : "=l"(e1) : "f"(a0), "f"(a1));
        asm("mov.b64 %0, {%1, %2};" : "=l"(e2) : "f"(b0), "f"(b1));
        asm("mov.b64 %0, {%1, %2};" : "=l"(e3) : "f"(s0), "f"(s1));
        T[p * 24      + k] = 0ull;
        T[p * 24 +  6 + k] = e1;
        T[p * 24 + 12 + k] = e2;
        T[p * 24 + 18 + k] = e3;
    }
    __syncthreads();

    int item = blockIdx.x * 256 + threadIdx.x;    // exactly BATCH*TSTEPS items
    int b = item / TSTEPS;
    int t = item - b * TSTEPS;

    // foldlike split: key_t = full output pair of threefry((0,42), (0,t))
    U2 kt = threefry2x32(0u, 42u, 0u, (unsigned)t);
    const unsigned k0 = kt.a, k1 = kt.b;
    const unsigned k2   = k0 ^ k1 ^ 0x1BD11BDAu;
    const unsigned k2p1 = k2 + 1u, k0p2 = k0 + 2u, k1p3 = k1 + 3u;
    const unsigned k2p4 = k2 + 4u, k0p5 = k0 + 5u;

    const unsigned idx0 = (unsigned)(b * NIN);
    const unsigned D = k1 + idx0;                 // x1 init base (counter folded)
    const unsigned E = k0 + k1 + idx0;            // x0 after round-1 add

    unsigned long long acc[5];
#pragma unroll
    for (int k = 0; k < 5; k++) acc[k] = 0ull;

    const unsigned* __restrict__ xip = g_xi + b * NIN;   // lane-shared -> broadcast
    const char* Tb = (const char*)T;

    for (int i0 = 0; i0 < NIN; i0 += 8) {         // 4 pairs per iter
        uint4 xiA = *(const uint4*)(xip + i0);
        uint4 xiB = *(const uint4*)(xip + i0 + 4);
#pragma unroll
        for (int q = 0; q < 4; q++) {
            unsigned xia = (q == 0) ? xiA.x : (q == 1) ? xiA.z
                         : (q == 2) ? xiB.x : xiB.z;
            unsigned xib = (q == 0) ? xiA.y : (q == 1) ? xiA.w
                         : (q == 2) ? xiB.y : xiB.w;
            unsigned i = (unsigned)(i0 + 2 * q);
            // uniform A: counter j = idx0 + i
            unsigned x1 = D + i, x0 = E + i;      // round-1 add folded
            x1 = rotl32(x1, 13) ^ x0;
            RND(x0, x1, 15) RND(x0, x1, 26) RND(x0, x1, 6)
            x0 += k1; x1 += k2p1;
            RND(x0, x1, 17) RND(x0, x1, 29) RND(x0, x1, 16) RND(x0, x1, 24)
            x0 += k2; x1 += k0p2;
            RND(x0, x1, 13) RND(x0, x1, 15) RND(x0, x1, 26) RND(x0, x1, 6)
            x0 += k0; x1 += k1p3;
            RND(x0, x1, 17) RND(x0, x1, 29) RND(x0, x1, 16) RND(x0, x1, 24)
            x0 += k1; x1 += k2p4;
            RND(x0, x1, 13) RND(x0, x1, 15) RND(x0, x1, 26) RND(x0, x1, 6)
            x0 += k2; x1 += k0p5;
            unsigned bitsA = x0 ^ x1;
            // uniform B: counter j = idx0 + i + 1
            unsigned y1 = D + i + 1u, y0 = E + i + 1u;
            y1 = rotl32(y1, 13) ^ y0;
            RND(y0, y1, 15) RND(y0, y1, 26) RND(y0, y1, 6)
            y0 += k1; y1 += k2p1;
            RND(y0, y1, 17) RND(y0, y1, 29) RND(y0, y1, 16) RND(y0, y1, 24)
            y0 += k2; y1 += k0p2;
            RND(y0, y1, 13) RND(y0, y1, 15) RND(y0, y1, 26) RND(y0, y1, 6)
            y0 += k0; y1 += k1p3;
            RND(y0, y1, 17) RND(y0, y1, 29) RND(y0, y1, 16) RND(y0, y1, 24)
            y0 += k1; y1 += k2p4;
            RND(y0, y1, 13) RND(y0, y1, 15) RND(y0, y1, 26) RND(y0, y1, 6)
            y0 += k2; y1 += k0p5;
            unsigned bitsB = y0 ^ y1;

            unsigned off = (bitsA < xia ? 48u : 0u) + (bitsB < xib ? 96u : 0u);
            const unsigned long long* e = (const unsigned long long*)
                (Tb + (unsigned)(i0 / 2 + q) * 192u + off);
            ulonglong2 w01 = *(const ulonglong2*)e;        // LDS.128
            ulonglong2 w23 = *(const ulonglong2*)(e + 2);  // LDS.128
            unsigned long long w4 = e[4];                  // LDS.64
            asm("add.rn.f32x2 %0, %0, %1;" : "+l"(acc[0]) : "l"(w01.x));
            asm("add.rn.f32x2 %0, %0, %1;" : "+l"(acc[1]) : "l"(w01.y));
            asm("add.rn.f32x2 %0, %0, %1;" : "+l"(acc[2]) : "l"(w23.x));
            asm("add.rn.f32x2 %0, %0, %1;" : "+l"(acc[3]) : "l"(w23.y));
            asm("add.rn.f32x2 %0, %0, %1;" : "+l"(acc[4]) : "l"(w4));
        }
    }

    // I[t][b][0..9], padded stride 12 -> base byte offset multiple of 48
    unsigned long long* dst =
        (unsigned long long*)(g_I + ((size_t)t * BATCH + b) * IPAD);
#pragma unroll
    for (int k = 0; k < 5; k++) dst[k] = acc[k];
}

// ---------------- phase 2: LIF scan over t, per (b,o) ----------------
__global__ __launch_bounds__(256) void snn_phase2(float* __restrict__ out) {
    int id = blockIdx.x * 256 + threadIdx.x;
    if (id >= BATCH * NOUT) return;
    int b = id / NOUT, o = id - b * NOUT;
    const float* __restrict__ src = g_I + (size_t)b * IPAD + o;

    float v = 0.0f, acc = 0.0f;
#pragma unroll 4
    for (int t = 0; t < TSTEPS; t++) {
        float I = src[(size_t)t * BATCH * IPAD];
        v = v + (I - v) * 0.5f;          // /2.0 == *0.5 exactly
        if (v >= 1.0f) { acc += 1.0f; v = 0.0f; }   // sign-exact vs (v-1>=0)
    }
    out[id] = __fdiv_rn(acc, 100.0f);    // IEEE div regardless of fast-math flags
}

// ---------------- launch ----------------
extern "C" void kernel_launch(void* const* d_in, const int* in_sizes, int n_in,
                              void* d_out, int out_size) {
    const float* x = (const float*)d_in[0];
    const float* W = (const float*)d_in[1];
    if (n_in >= 2 && in_sizes[0] == NOUT * NIN) {   // order robustness
        W = (const float*)d_in[0];
        x = (const float*)d_in[1];
    }
    float* out = (float*)d_out;               // [16384,10]

    const int smem = NPAIR * 24 * 8;          // 75,264 B dynamic shared
    cudaFuncSetAttribute(snn_phase1,
                         cudaFuncAttributeMaxDynamicSharedMemorySize, smem);

    snn_prep  <<<(BATCH * NIN + 255) / 256, 256>>>(x);
    snn_phase1<<<(BATCH * TSTEPS) / 256,    256, smem>>>(W);
    snn_phase2<<<(BATCH * NOUT + 255) / 256, 256>>>(out);
}